// round 12
// baseline (speedup 1.0000x reference)
#include <cuda_runtime.h>
#include <cuda_bf16.h>
#include <cstdint>
#include <cstddef>

// Problem dims
#define Nn 256
#define Tt 128
#define Dd 512
#define Hh 1024
#define G4 4096            // 4*H
#define Ktot 2560          // W^T cols: Wh (0..1023) | Wattn (1024..2047) | Wx (2048..2559)
#define KSTEP 1536         // per-step GEMM K: h (0..1023) | x_t (1024..1535)

#define NBLK 444           // persistent grid: 148 SMs x 3 CTAs, ALL GEMM workers
#define NCHUNK_TOT 6144    // 64 bn x 2 bm x 48 k-chunks (GBK=32)
#define NSLOT 5            // max partial-writers per (bn,bm) group

// ---------------- scratch (device globals: allocation-free rule) ----------------
__device__ float g_c[Nn * Hh];                          // LSTM cell state (fp32)
__device__ float g_h[Nn * Hh];                          // current h (fp32)
__device__ float g_gp[(size_t)NSLOT * Nn * G4];         // per-step GEMM partial slots
__device__ float g_pa[(size_t)Nn * G4];                 // attn contribution to gates
__device__ float g_P[(size_t)Nn * 16 * G4];             // P[(n,l)][col] = A[n,:,l] @ Wattn
__device__ __nv_bfloat16 g_Ahi[(size_t)Nn * Hh];        // h hi
__device__ __nv_bfloat16 g_Alo[(size_t)Nn * Hh];        // h lo
__device__ __nv_bfloat16 g_AThi[(size_t)Nn * 16 * Hh];  // A^T [(n,l)][h] hi
__device__ __nv_bfloat16 g_ATlo[(size_t)Nn * 16 * Hh];  // A^T [(n,l)][h] lo
__device__ __nv_bfloat16 g_xhi[(size_t)Nn * Tt * Dd];   // x hi
__device__ __nv_bfloat16 g_xlo[(size_t)Nn * Tt * Dd];   // x lo
__device__ __nv_bfloat16 g_WThi[(size_t)G4 * Ktot];     // W^T hi: [n][k], K-major
__device__ __nv_bfloat16 g_WTlo[(size_t)G4 * Ktot];     // W^T lo

// grid barrier state
__device__ unsigned g_bar_count = 0;
__device__ unsigned g_bar_gen = 0;

// ---------------- worker chunk partition ----------------
// worker w in [0,444): start chunk C(w). 372 workers get 14 chunks, 72 get 13.
// C(w) = 14w for w <= 372, else 5208 + 13(w-372).  C(444) = 6144.
__device__ __forceinline__ int cstart(int w) {
    return (w <= 372) ? 14 * w : 5208 + 13 * (w - 372);
}
// worker whose range contains chunk c
__device__ __forceinline__ int wof(int c) {
    return (c < 5208) ? (c / 14) : (372 + (c - 5208) / 13);
}

// ---------------- PTX helpers (sm_80+ baseline features only) ----------------
__device__ __forceinline__ uint32_t smem_to_u32(const void* p) {
    uint32_t a;
    asm("{ .reg .u64 t; cvta.to.shared.u64 t, %1; cvt.u32.u64 %0, t; }" : "=r"(a) : "l"(p));
    return a;
}
#define CP_ASYNC16(dst, src) \
    asm volatile("cp.async.cg.shared.global [%0], [%1], 16;" :: "r"(dst), "l"(src))
#define CP_COMMIT() asm volatile("cp.async.commit_group;" ::: "memory")
#define CP_WAIT0()  asm volatile("cp.async.wait_group 0;" ::: "memory")
#define LDSM_X4(r0, r1, r2, r3, addr)                                             \
    asm volatile("ldmatrix.sync.aligned.m8n8.x4.shared.b16 {%0,%1,%2,%3}, [%4];"  \
        : "=r"(r0), "=r"(r1), "=r"(r2), "=r"(r3) : "r"(addr))

__device__ __forceinline__ void mma16816(float* c, const uint32_t* a,
                                         uint32_t b0, uint32_t b1) {
    asm volatile(
        "mma.sync.aligned.m16n8k16.row.col.f32.bf16.bf16.f32 "
        "{%0,%1,%2,%3}, {%4,%5,%6,%7}, {%8,%9}, {%0,%1,%2,%3};"
        : "+f"(c[0]), "+f"(c[1]), "+f"(c[2]), "+f"(c[3])
        : "r"(a[0]), "r"(a[1]), "r"(a[2]), "r"(a[3]), "r"(b0), "r"(b1));
}

// Software grid barrier. Safe: all NBLK CTAs co-resident (444 = 148 SMs x 3).
__device__ __forceinline__ void grid_sync() {
    __syncthreads();
    if (threadIdx.x == 0) {
        __threadfence();
        unsigned g = *(volatile unsigned*)&g_bar_gen;
        unsigned prev = atomicAdd(&g_bar_count, 1u);
        if (prev == NBLK - 1) {
            g_bar_count = 0;
            __threadfence();
            *(volatile unsigned*)&g_bar_gen = g + 1;
        } else {
            while (*(volatile unsigned*)&g_bar_gen == g) { __nanosleep(64); }
        }
    }
    __syncthreads();
}

// ---------------- math helpers ----------------
__device__ __forceinline__ float sigmoidf_(float x) { return 1.0f / (1.0f + __expf(-x)); }
__device__ __forceinline__ float tanhf_(float x) {
    float e = __expf(2.0f * x);
    return 1.0f - 2.0f / (e + 1.0f);
}
__device__ __forceinline__ void split_bf16(float v, __nv_bfloat16& hi, __nv_bfloat16& lo) {
    hi = __float2bfloat16(v);
    lo = __float2bfloat16(v - __bfloat162float(hi));
}

// ---------------- shared GEMM tiling ----------------
#define GBM 128
#define GBN 64
#define GBK 32
#define RSTR 80              // smem row stride bytes (32 bf16 + 8 pad)
#define STG 30720            // bytes per pipeline stage
#define AH_OFF(s) ((s) * STG)
#define AL_OFF(s) ((s) * STG + 10240)
#define BH_OFF(s) ((s) * STG + 20480)
#define BL_OFF(s) ((s) * STG + 25600)
#define SMEM_DYN (2 * STG)   // 61440 -> 3 CTAs/SM

// Fragment compute for one chunk stage.
__device__ __forceinline__ void compute_chunk(uint32_t s0, int stage,
                                              uint32_t aOff, uint32_t bOff,
                                              float acc[2][4][4])
{
    const uint32_t ah = s0 + AH_OFF(stage) + aOff;
    const uint32_t al = s0 + AL_OFF(stage) + aOff;
    const uint32_t bh = s0 + BH_OFF(stage) + bOff;
    const uint32_t bl = s0 + BL_OFF(stage) + bOff;
#pragma unroll
    for (int ks = 0; ks < 2; ks++) {
        const uint32_t ko = ks * 32;   // 16 elems * 2B
        uint32_t ahf[2][4], alf[2][4];
        uint32_t bhf[2][4], blf[2][4];
        LDSM_X4(ahf[0][0], ahf[0][1], ahf[0][2], ahf[0][3], ah + ko);
        LDSM_X4(ahf[1][0], ahf[1][1], ahf[1][2], ahf[1][3], ah + 16 * RSTR + ko);
        LDSM_X4(bhf[0][0], bhf[0][1], bhf[0][2], bhf[0][3], bh + ko);
        LDSM_X4(bhf[1][0], bhf[1][1], bhf[1][2], bhf[1][3], bh + 16 * RSTR + ko);
        LDSM_X4(blf[0][0], blf[0][1], blf[0][2], blf[0][3], bl + ko);
        LDSM_X4(blf[1][0], blf[1][1], blf[1][2], blf[1][3], bl + 16 * RSTR + ko);
        LDSM_X4(alf[0][0], alf[0][1], alf[0][2], alf[0][3], al + ko);
        LDSM_X4(alf[1][0], alf[1][1], alf[1][2], alf[1][3], al + 16 * RSTR + ko);
#pragma unroll
        for (int mf = 0; mf < 2; mf++) {
#pragma unroll
            for (int nf = 0; nf < 4; nf++) {
                const uint32_t b0 = bhf[nf >> 1][(nf & 1) * 2];
                const uint32_t b1 = bhf[nf >> 1][(nf & 1) * 2 + 1];
                mma16816(acc[mf][nf], ahf[mf], b0, b1);           // hi*hi
                mma16816(acc[mf][nf], alf[mf], b0, b1);           // lo*hi
                mma16816(acc[mf][nf], ahf[mf],                    // hi*lo
                         blf[nf >> 1][(nf & 1) * 2], blf[nf >> 1][(nf & 1) * 2 + 1]);
            }
        }
    }
}

// =====================================================================
// One-time: W^T hi/lo. WT[n][k] = bf16split(W[k][n]); K rows: Wh|Wattn|Wx
// =====================================================================
__global__ __launch_bounds__(256) void wconv_kernel(const float* __restrict__ Wx,
                                                    const float* __restrict__ Wh,
                                                    const float* __restrict__ Wattn)
{
    __shared__ float tile[32][33];
    const int nt = blockIdx.x * 32;
    const int kt = blockIdx.y * 32;
    const int tx = threadIdx.x & 31, ty = threadIdx.x >> 5;
#pragma unroll
    for (int r = 0; r < 4; r++) {
        int k = kt + ty + r * 8;
        int n = nt + tx;
        const float* src;
        if (k < 1024)       src = Wh    + (size_t)k * G4;
        else if (k < 2048)  src = Wattn + (size_t)(k - 1024) * G4;
        else                src = Wx    + (size_t)(k - 2048) * G4;
        tile[ty + r * 8][tx] = src[n];
    }
    __syncthreads();
#pragma unroll
    for (int r = 0; r < 4; r++) {
        int n = nt + ty + r * 8;
        int k = kt + tx;
        float v = tile[tx][ty + r * 8];
        __nv_bfloat16 hi, lo;
        split_bf16(v, hi, lo);
        g_WThi[(size_t)n * Ktot + k] = hi;
        g_WTlo[(size_t)n * Ktot + k] = lo;
    }
}

// One-time: x -> bf16 hi/lo
__global__ __launch_bounds__(256) void xconv_kernel(const float* __restrict__ x)
{
    const size_t total = (size_t)Nn * Tt * Dd;
    for (size_t i = (size_t)blockIdx.x * blockDim.x + threadIdx.x; i < total;
         i += (size_t)gridDim.x * blockDim.x) {
        __nv_bfloat16 hi, lo;
        split_bf16(x[i], hi, lo);
        g_xhi[i] = hi;
        g_xlo[i] = lo;
    }
}

// One-time: A[n][h][l] -> A^T [(n*16+l)][h] bf16 hi/lo
__global__ __launch_bounds__(256) void aconv_kernel(const float* __restrict__ A)
{
    const int n = blockIdx.x;
    const float* An = A + (size_t)n * Hh * 16;
    for (int idx = threadIdx.x; idx < Hh * 16; idx += 256) {
        const int h = idx >> 4, l = idx & 15;
        __nv_bfloat16 hi, lo;
        split_bf16(An[idx], hi, lo);
        const size_t o = ((size_t)(n * 16 + l)) * Hh + h;
        g_AThi[o] = hi;
        g_ATlo[o] = lo;
    }
}

// =====================================================================
// One-time GEMM: P[(n,l)][:] = A^T[(n,l)][:] @ Wattn  (bf16 hi/lo x3)
// =====================================================================
__global__ __launch_bounds__(256, 3) void gemm_P_kernel()
{
    extern __shared__ __align__(128) __nv_bfloat16 dsm[];
    const uint32_t s0 = smem_to_u32(dsm);
    const int tid = threadIdx.x;
    const int lane = tid & 31;
    const int w = tid >> 5;
    const int wm = w & 3, wn = w >> 2;
    const int bn = blockIdx.x * GBN;
    const int bm = blockIdx.y * GBM;

    const int a_row = tid >> 2, a_seg = tid & 3;
    const int b_row = tid >> 2, b_seg = tid & 3;
    const uint32_t aOff = (uint32_t)((wm * 32 + (lane & 15)) * RSTR + (lane >> 4) * 16);
    const int brow = (lane & 7) + ((lane >> 4) << 3);
    const uint32_t bOff = (uint32_t)((wn * 32 + brow) * RSTR + ((lane >> 3) & 1) * 16);

    auto issue = [&](int c, int s) {
        const int kc = c * GBK;
        {
            const size_t o = (size_t)(bn + b_row) * Ktot + 1024 + kc + b_seg * 8;
            CP_ASYNC16(s0 + BH_OFF(s) + b_row * RSTR + b_seg * 16, g_WThi + o);
            CP_ASYNC16(s0 + BL_OFF(s) + b_row * RSTR + b_seg * 16, g_WTlo + o);
        }
#pragma unroll
        for (int r = 0; r < 2; r++) {
            const int m = a_row + r * 64;
            const size_t o = (size_t)(bm + m) * Hh + kc + a_seg * 8;
            const uint32_t d = m * RSTR + a_seg * 16;
            CP_ASYNC16(s0 + AH_OFF(s) + d, g_AThi + o);
            CP_ASYNC16(s0 + AL_OFF(s) + d, g_ATlo + o);
        }
    };

    float acc[2][4][4];
#pragma unroll
    for (int mf = 0; mf < 2; mf++)
#pragma unroll
        for (int nf = 0; nf < 4; nf++)
#pragma unroll
            for (int i = 0; i < 4; i++) acc[mf][nf][i] = 0.0f;

    const int NCH = Hh / GBK;  // 32
    issue(0, 0); CP_COMMIT();
    for (int it = 0; it < NCH; it++) {
        CP_WAIT0();
        __syncthreads();
        if (it + 1 < NCH) { issue(it + 1, (it + 1) & 1); CP_COMMIT(); }
        compute_chunk(s0, it & 1, aOff, bOff, acc);
    }

#pragma unroll
    for (int mf = 0; mf < 2; mf++) {
        const int row0 = bm + wm * 32 + mf * 16 + (lane >> 2);
#pragma unroll
        for (int nf = 0; nf < 4; nf++) {
            const int col = bn + wn * 32 + nf * 8 + (lane & 3) * 2;
            *(float2*)&g_P[(size_t)row0 * G4 + col] =
                make_float2(acc[mf][nf][0], acc[mf][nf][1]);
            *(float2*)&g_P[(size_t)(row0 + 8) * G4 + col] =
                make_float2(acc[mf][nf][2], acc[mf][nf][3]);
        }
    }
}

// =====================================================================
// Init: h0 = mean_l A[n,h,l]; c0 = h0; write g_h fp32 + bf16 hi/lo.
// =====================================================================
__global__ __launch_bounds__(256) void init_kernel(const float* __restrict__ A)
{
    int n = blockIdx.x;
    int tid = threadIdx.x;
    const float* An = A + (size_t)n * Hh * 16;

#pragma unroll
    for (int r = 0; r < 4; r++) {
        int hh = tid + r * 256;
        const float4* ar = (const float4*)(An + (size_t)hh * 16);
        float4 a0 = ar[0], a1 = ar[1], a2 = ar[2], a3 = ar[3];
        float s = a0.x + a0.y + a0.z + a0.w + a1.x + a1.y + a1.z + a1.w
                + a2.x + a2.y + a2.z + a2.w + a3.x + a3.y + a3.z + a3.w;
        s *= (1.0f / 16.0f);
        g_c[(size_t)n * Hh + hh] = s;
        g_h[(size_t)n * Hh + hh] = s;
        __nv_bfloat16 hi, lo;
        split_bf16(s, hi, lo);
        g_Ahi[(size_t)n * Hh + hh] = hi;
        g_Alo[(size_t)n * Hh + hh] = lo;
    }
}

// =====================================================================
// Persistent step loop: 444 CTAs (148 SMs x 3), all resident.
// Phase 1: every CTA is a GEMM worker over chunk range [C(w), C(w+1))
//          (13-14 chunks of the 6144-chunk global space); light workers
//          (w >= 372, 13 chunks) also run attention for 3-4 batch rows.
// Phase 2 (after grid_sync): cooperative LSTM pointwise summing the
//          deterministic partial slots + pa + b; grid_sync; next t.
// =====================================================================
__global__ __launch_bounds__(256, 3) void step_loop_kernel(const float* __restrict__ A,
                                                           const float* __restrict__ b,
                                                           float* __restrict__ out)
{
    extern __shared__ __align__(128) __nv_bfloat16 dsm[];
    __shared__ float red[16][8];
    __shared__ float wsm[16];

    const uint32_t s0 = smem_to_u32(dsm);
    const int tid = threadIdx.x;
    const int lane = tid & 31;
    const int bx = blockIdx.x;

    // GEMM-role constants
    const int w = tid >> 5;
    const int wm = w & 3, wn = w >> 2;
    const int a_row = tid >> 2, a_seg = tid & 3;
    const int b_row = tid >> 2, b_seg = tid & 3;
    const uint32_t aOff = (uint32_t)((wm * 32 + (lane & 15)) * RSTR + (lane >> 4) * 16);
    const int brow_l = (lane & 7) + ((lane >> 4) << 3);
    const uint32_t bOff = (uint32_t)((wn * 32 + brow_l) * RSTR + ((lane >> 3) & 1) * 16);

    const int c0 = cstart(bx);
    const int c1 = cstart(bx + 1);

    for (int t = 0; t < Tt; t++) {
        // ---------------- attention (light workers only) ----------------
        if (bx >= 372) {
            const int a_id = bx - 372;            // 0..71
            const int n0 = (a_id * 256) / 72;
            const int n1 = ((a_id + 1) * 256) / 72;
#pragma unroll 1
            for (int n = n0; n < n1; n++) {
                const float* An = A + (size_t)n * Hh * 16;
                const float* hn = g_h + (size_t)n * Hh;

                float sc[16];
#pragma unroll
                for (int l = 0; l < 16; l++) sc[l] = 0.0f;
#pragma unroll
                for (int r = 0; r < 4; r++) {
                    int hh = tid + r * 256;
                    float hv = hn[hh];
                    const float4* ar = (const float4*)(An + (size_t)hh * 16);
                    float4 a0 = ar[0], a1 = ar[1], a2 = ar[2], a3 = ar[3];
                    sc[0]  += a0.x * hv; sc[1]  += a0.y * hv; sc[2]  += a0.z * hv; sc[3]  += a0.w * hv;
                    sc[4]  += a1.x * hv; sc[5]  += a1.y * hv; sc[6]  += a1.z * hv; sc[7]  += a1.w * hv;
                    sc[8]  += a2.x * hv; sc[9]  += a2.y * hv; sc[10] += a2.z * hv; sc[11] += a2.w * hv;
                    sc[12] += a3.x * hv; sc[13] += a3.y * hv; sc[14] += a3.z * hv; sc[15] += a3.w * hv;
                }
#pragma unroll
                for (int l = 0; l < 16; l++) {
#pragma unroll
                    for (int off = 16; off > 0; off >>= 1)
                        sc[l] += __shfl_xor_sync(0xffffffffu, sc[l], off);
                }
                int warp = tid >> 5;
                if (lane == 0) {
#pragma unroll
                    for (int l = 0; l < 16; l++) red[l][warp] = sc[l];
                }
                __syncthreads();
                if (tid == 0) {
                    float s[16];
                    float mx = -1e30f;
#pragma unroll
                    for (int l = 0; l < 16; l++) {
                        float v = 0.0f;
#pragma unroll
                        for (int w2 = 0; w2 < 8; w2++) v += red[l][w2];
                        v *= 0.03125f;  // 1/sqrt(1024)
                        s[l] = v;
                        mx = fmaxf(mx, v);
                    }
                    float sum = 0.0f;
#pragma unroll
                    for (int l = 0; l < 16; l++) { float e = __expf(s[l] - mx); s[l] = e; sum += e; }
                    float inv = 1.0f / sum;
#pragma unroll
                    for (int l = 0; l < 16; l++) wsm[l] = s[l] * inv;
                }
                __syncthreads();

                float s[16];
#pragma unroll
                for (int i = 0; i < 16; i++) s[i] = 0.0f;
#pragma unroll
                for (int l = 0; l < 16; l++) {
                    const float wl = wsm[l];
                    const float* Pr = g_P + ((size_t)(n * 16 + l)) * G4;
#pragma unroll
                    for (int i = 0; i < 16; i++) s[i] += wl * Pr[tid + i * 256];
                }
                float* pa = g_pa + (size_t)n * G4;
#pragma unroll
                for (int i = 0; i < 16; i++) pa[tid + i * 256] = s[i];
                __syncthreads();
            }
        }

        // ---------------- GEMM over chunk range [c0, c1) ----------------
        {
            auto issue = [&](int c, int s) {
                const int g = c / 48;
                const int kk = (c - g * 48) * GBK;         // 0..1535 within step-K
                const int bn = (g >> 1) * GBN;
                const int bm = (g & 1) * GBM;
                const int kidx = (kk < 1024) ? kk : kk + 1024;  // WT column
                {
                    const size_t o = (size_t)(bn + b_row) * Ktot + kidx + b_seg * 8;
                    CP_ASYNC16(s0 + BH_OFF(s) + b_row * RSTR + b_seg * 16, g_WThi + o);
                    CP_ASYNC16(s0 + BL_OFF(s) + b_row * RSTR + b_seg * 16, g_WTlo + o);
                }
#pragma unroll
                for (int r = 0; r < 2; r++) {
                    const int m = a_row + r * 64;
                    const __nv_bfloat16 *sh, *sl;
                    if (kk < 1024) {
                        const size_t o = (size_t)(bm + m) * Hh + kk + a_seg * 8;
                        sh = g_Ahi + o; sl = g_Alo + o;
                    } else {
                        const size_t o = (size_t)(bm + m) * (Tt * Dd) + (size_t)t * Dd
                                       + (kk - 1024) + a_seg * 8;
                        sh = g_xhi + o; sl = g_xlo + o;
                    }
                    const uint32_t d = m * RSTR + a_seg * 16;
                    CP_ASYNC16(s0 + AH_OFF(s) + d, sh);
                    CP_ASYNC16(s0 + AL_OFF(s) + d, sl);
                }
            };

            float acc[2][4][4];
#pragma unroll
            for (int mf = 0; mf < 2; mf++)
#pragma unroll
                for (int nf = 0; nf < 4; nf++)
#pragma unroll
                    for (int i = 0; i < 4; i++) acc[mf][nf][i] = 0.0f;

            issue(c0, 0); CP_COMMIT();
            for (int c = c0; c < c1; c++) {
                CP_WAIT0();
                __syncthreads();
                if (c + 1 < c1) { issue(c + 1, (c + 1 - c0) & 1); CP_COMMIT(); }
                compute_chunk(s0, (c - c0) & 1, aOff, bOff, acc);

                // flush at group boundary or range end
                if (c + 1 == c1 || (c + 1) / 48 != c / 48) {
                    const int g = c / 48;
                    const int slot = bx - wof(g * 48);
                    const int bn = (g >> 1) * GBN;
                    const int bm = (g & 1) * GBM;
                    float* gpart = g_gp + (size_t)slot * Nn * G4;
#pragma unroll
                    for (int mf = 0; mf < 2; mf++) {
                        const int row0 = bm + wm * 32 + mf * 16 + (lane >> 2);
#pragma unroll
                        for (int nf = 0; nf < 4; nf++) {
                            const int col = bn + wn * 32 + nf * 8 + (lane & 3) * 2;
                            *(float2*)&gpart[(size_t)row0 * G4 + col] =
                                make_float2(acc[mf][nf][0], acc[mf][nf][1]);
                            *(float2*)&gpart[(size_t)(row0 + 8) * G4 + col] =
                                make_float2(acc[mf][nf][2], acc[mf][nf][3]);
                        }
                    }
                    if (c + 1 < c1) {
#pragma unroll
                        for (int mf = 0; mf < 2; mf++)
#pragma unroll
                            for (int nf = 0; nf < 4; nf++)
#pragma unroll
                                for (int i = 0; i < 4; i++) acc[mf][nf][i] = 0.0f;
                    }
                }
            }
        }

        grid_sync();   // all partials + pa complete and visible

        // ---------------- cooperative LSTM pointwise ----------------
        for (int e = bx * 256 + tid; e < Nn * Hh; e += NBLK * 256) {
            const int n = e >> 10;
            const int hh = e & 1023;
            float gv[4];
#pragma unroll
            for (int gg = 0; gg < 4; gg++) {
                const int col = gg * Hh + hh;
                const int g = (col >> 6) * 2 + (n >> 7);
                const int wf = wof(g * 48);
                const int wl = wof(g * 48 + 47);
                float s = g_pa[(size_t)n * G4 + col] + b[col];
                const float* gp = g_gp + (size_t)n * G4 + col;
#pragma unroll 1
                for (int sl = 0; sl <= wl - wf; sl++)
                    s += gp[(size_t)sl * Nn * G4];
                gv[gg] = s;
            }
            float c = g_c[e];
            float cn = sigmoidf_(gv[1]) * c + sigmoidf_(gv[0]) * tanhf_(gv[3]);
            float hn = sigmoidf_(gv[2]) * tanhf_(cn);
            g_c[e] = cn;
            g_h[e] = hn;
            out[(size_t)n * Tt * Hh + (size_t)t * Hh + hh] = hn;
            __nv_bfloat16 hi, lo;
            split_bf16(hn, hi, lo);
            g_Ahi[e] = hi;
            g_Alo[e] = lo;
        }

        grid_sync();   // h_{t+1} visible to everyone
    }
}

// =====================================================================
// launch
// =====================================================================
extern "C" void kernel_launch(void* const* d_in, const int* in_sizes, int n_in,
                              void* d_out, int out_size)
{
    (void)in_sizes; (void)n_in; (void)out_size;
    const float* x     = (const float*)d_in[0];  // (N, T, D)
    const float* A     = (const float*)d_in[1];  // (N, H, 4, 4)
    const float* Wx    = (const float*)d_in[2];  // (D, 4H)
    const float* Wh    = (const float*)d_in[3];  // (H, 4H)
    const float* Wattn = (const float*)d_in[4];  // (H, 4H)
    const float* b     = (const float*)d_in[5];  // (4H,)
    float* out = (float*)d_out;                  // (N, T, H)

    cudaFuncSetAttribute(gemm_P_kernel,
                         cudaFuncAttributeMaxDynamicSharedMemorySize, SMEM_DYN);
    cudaFuncSetAttribute(step_loop_kernel,
                         cudaFuncAttributeMaxDynamicSharedMemorySize, SMEM_DYN);

    // one-time prep
    dim3 wgrid(G4 / 32, Ktot / 32);
    wconv_kernel<<<wgrid, 256>>>(Wx, Wh, Wattn);
    xconv_kernel<<<8192, 256>>>(x);
    aconv_kernel<<<Nn, 256>>>(A);
    gemm_P_kernel<<<dim3(G4 / GBN, (Nn * 16) / GBM), 256, SMEM_DYN>>>();
    init_kernel<<<Nn, 256>>>(A);

    // the whole 128-step recurrence in ONE persistent launch
    step_loop_kernel<<<NBLK, 256, SMEM_DYN>>>(A, b, out);
}

// round 13
// speedup vs baseline: 1.3369x; 1.3369x over previous
#include <cuda_runtime.h>
#include <cuda_bf16.h>
#include <cstdint>
#include <cstddef>

// Problem dims
#define Nn 256
#define Tt 128
#define Dd 512
#define Hh 1024
#define G4 4096            // 4*H
#define Ktot 2560          // W^T cols: Wh (0..1023) | Wattn (1024..2047) | Wx (2048..2559)
#define KSTEP 1536         // per-step GEMM K: h (0..1023) | x_t (1024..1535)

#define NBLK 444           // persistent grid: 384 GEMM + 60 attn = 148 SMs x 3 (all resident)
#define NGEMM 384          // 64 bn x 2 bm x 3 kz
#define NATT  60

// ---------------- scratch (device globals: allocation-free rule) ----------------
__device__ float g_c[Nn * Hh];                          // LSTM cell state (fp32)
__device__ float g_h[Nn * Hh];                          // current h (fp32)
__device__ float g_gp[(size_t)3 * Nn * G4];             // per-step GEMM partials (3 K-splits)
__device__ float g_pa[(size_t)Nn * G4];                 // attn contribution to gates
__device__ float g_P[(size_t)Nn * 16 * G4];             // P[(n,l)][col] = A[n,:,l] @ Wattn
__device__ __nv_bfloat16 g_Ahi[(size_t)Nn * Hh];        // h hi
__device__ __nv_bfloat16 g_Alo[(size_t)Nn * Hh];        // h lo
__device__ __nv_bfloat16 g_AThi[(size_t)Nn * 16 * Hh];  // A^T [(n,l)][h] hi
__device__ __nv_bfloat16 g_ATlo[(size_t)Nn * 16 * Hh];  // A^T [(n,l)][h] lo
__device__ __nv_bfloat16 g_xhi[(size_t)Nn * Tt * Dd];   // x hi
__device__ __nv_bfloat16 g_xlo[(size_t)Nn * Tt * Dd];   // x lo
__device__ __nv_bfloat16 g_WThi[(size_t)G4 * Ktot];     // W^T hi: [n][k], K-major
__device__ __nv_bfloat16 g_WTlo[(size_t)G4 * Ktot];     // W^T lo

// grid barrier state
__device__ unsigned g_bar_count = 0;
__device__ unsigned g_bar_gen = 0;

// ---------------- PTX helpers (sm_80+ baseline features only) ----------------
__device__ __forceinline__ uint32_t smem_to_u32(const void* p) {
    uint32_t a;
    asm("{ .reg .u64 t; cvta.to.shared.u64 t, %1; cvt.u32.u64 %0, t; }" : "=r"(a) : "l"(p));
    return a;
}
#define CP_ASYNC16(dst, src) \
    asm volatile("cp.async.cg.shared.global [%0], [%1], 16;" :: "r"(dst), "l"(src))
#define CP_COMMIT() asm volatile("cp.async.commit_group;" ::: "memory")
#define CP_WAIT0()  asm volatile("cp.async.wait_group 0;" ::: "memory")
#define LDSM_X4(r0, r1, r2, r3, addr)                                             \
    asm volatile("ldmatrix.sync.aligned.m8n8.x4.shared.b16 {%0,%1,%2,%3}, [%4];"  \
        : "=r"(r0), "=r"(r1), "=r"(r2), "=r"(r3) : "r"(addr))

__device__ __forceinline__ void mma16816(float* c, const uint32_t* a,
                                         uint32_t b0, uint32_t b1) {
    asm volatile(
        "mma.sync.aligned.m16n8k16.row.col.f32.bf16.bf16.f32 "
        "{%0,%1,%2,%3}, {%4,%5,%6,%7}, {%8,%9}, {%0,%1,%2,%3};"
        : "+f"(c[0]), "+f"(c[1]), "+f"(c[2]), "+f"(c[3])
        : "r"(a[0]), "r"(a[1]), "r"(a[2]), "r"(a[3]), "r"(b0), "r"(b1));
}

// Software grid barrier. Safe: all NBLK CTAs co-resident (444 = 148 SMs x 3).
__device__ __forceinline__ void grid_sync() {
    __syncthreads();
    if (threadIdx.x == 0) {
        __threadfence();
        unsigned g = *(volatile unsigned*)&g_bar_gen;
        unsigned prev = atomicAdd(&g_bar_count, 1u);
        if (prev == NBLK - 1) {
            g_bar_count = 0;
            __threadfence();
            *(volatile unsigned*)&g_bar_gen = g + 1;
        } else {
            while (*(volatile unsigned*)&g_bar_gen == g) { __nanosleep(64); }
        }
    }
    __syncthreads();
}

// ---------------- math helpers ----------------
__device__ __forceinline__ float sigmoidf_(float x) { return 1.0f / (1.0f + __expf(-x)); }
__device__ __forceinline__ float tanhf_(float x) {
    float e = __expf(2.0f * x);
    return 1.0f - 2.0f / (e + 1.0f);
}
__device__ __forceinline__ void split_bf16(float v, __nv_bfloat16& hi, __nv_bfloat16& lo) {
    hi = __float2bfloat16(v);
    lo = __float2bfloat16(v - __bfloat162float(hi));
}

// ---------------- shared GEMM tiling ----------------
#define GBM 128
#define GBN 64
#define GBK 32
#define RSTR 80              // smem row stride bytes (32 bf16 + 8 pad)
#define STG 30720            // bytes per pipeline stage
#define AH_OFF(s) ((s) * STG)
#define AL_OFF(s) ((s) * STG + 10240)
#define BH_OFF(s) ((s) * STG + 20480)
#define BL_OFF(s) ((s) * STG + 25600)
#define SMEM_DYN (2 * STG)   // 61440 -> 3 CTAs/SM

// Fragment compute for one chunk stage.
__device__ __forceinline__ void compute_chunk(uint32_t s0, int stage,
                                              uint32_t aOff, uint32_t bOff,
                                              float acc[2][4][4])
{
    const uint32_t ah = s0 + AH_OFF(stage) + aOff;
    const uint32_t al = s0 + AL_OFF(stage) + aOff;
    const uint32_t bh = s0 + BH_OFF(stage) + bOff;
    const uint32_t bl = s0 + BL_OFF(stage) + bOff;
#pragma unroll
    for (int ks = 0; ks < 2; ks++) {
        const uint32_t ko = ks * 32;   // 16 elems * 2B
        uint32_t ahf[2][4], alf[2][4];
        uint32_t bhf[2][4], blf[2][4];
        LDSM_X4(ahf[0][0], ahf[0][1], ahf[0][2], ahf[0][3], ah + ko);
        LDSM_X4(ahf[1][0], ahf[1][1], ahf[1][2], ahf[1][3], ah + 16 * RSTR + ko);
        LDSM_X4(bhf[0][0], bhf[0][1], bhf[0][2], bhf[0][3], bh + ko);
        LDSM_X4(bhf[1][0], bhf[1][1], bhf[1][2], bhf[1][3], bh + 16 * RSTR + ko);
        LDSM_X4(blf[0][0], blf[0][1], blf[0][2], blf[0][3], bl + ko);
        LDSM_X4(blf[1][0], blf[1][1], blf[1][2], blf[1][3], bl + 16 * RSTR + ko);
        LDSM_X4(alf[0][0], alf[0][1], alf[0][2], alf[0][3], al + ko);
        LDSM_X4(alf[1][0], alf[1][1], alf[1][2], alf[1][3], al + 16 * RSTR + ko);
#pragma unroll
        for (int mf = 0; mf < 2; mf++) {
#pragma unroll
            for (int nf = 0; nf < 4; nf++) {
                const uint32_t b0 = bhf[nf >> 1][(nf & 1) * 2];
                const uint32_t b1 = bhf[nf >> 1][(nf & 1) * 2 + 1];
                mma16816(acc[mf][nf], ahf[mf], b0, b1);           // hi*hi
                mma16816(acc[mf][nf], alf[mf], b0, b1);           // lo*hi
                mma16816(acc[mf][nf], ahf[mf],                    // hi*lo
                         blf[nf >> 1][(nf & 1) * 2], blf[nf >> 1][(nf & 1) * 2 + 1]);
            }
        }
    }
}

// =====================================================================
// One-time: W^T hi/lo. WT[n][k] = bf16split(W[k][n]); K rows: Wh|Wattn|Wx
// =====================================================================
__global__ __launch_bounds__(256) void wconv_kernel(const float* __restrict__ Wx,
                                                    const float* __restrict__ Wh,
                                                    const float* __restrict__ Wattn)
{
    __shared__ float tile[32][33];
    const int nt = blockIdx.x * 32;
    const int kt = blockIdx.y * 32;
    const int tx = threadIdx.x & 31, ty = threadIdx.x >> 5;
#pragma unroll
    for (int r = 0; r < 4; r++) {
        int k = kt + ty + r * 8;
        int n = nt + tx;
        const float* src;
        if (k < 1024)       src = Wh    + (size_t)k * G4;
        else if (k < 2048)  src = Wattn + (size_t)(k - 1024) * G4;
        else                src = Wx    + (size_t)(k - 2048) * G4;
        tile[ty + r * 8][tx] = src[n];
    }
    __syncthreads();
#pragma unroll
    for (int r = 0; r < 4; r++) {
        int n = nt + ty + r * 8;
        int k = kt + tx;
        float v = tile[tx][ty + r * 8];
        __nv_bfloat16 hi, lo;
        split_bf16(v, hi, lo);
        g_WThi[(size_t)n * Ktot + k] = hi;
        g_WTlo[(size_t)n * Ktot + k] = lo;
    }
}

// One-time: x -> bf16 hi/lo
__global__ __launch_bounds__(256) void xconv_kernel(const float* __restrict__ x)
{
    const size_t total = (size_t)Nn * Tt * Dd;
    for (size_t i = (size_t)blockIdx.x * blockDim.x + threadIdx.x; i < total;
         i += (size_t)gridDim.x * blockDim.x) {
        __nv_bfloat16 hi, lo;
        split_bf16(x[i], hi, lo);
        g_xhi[i] = hi;
        g_xlo[i] = lo;
    }
}

// One-time: A[n][h][l] -> A^T [(n*16+l)][h] bf16 hi/lo
__global__ __launch_bounds__(256) void aconv_kernel(const float* __restrict__ A)
{
    const int n = blockIdx.x;
    const float* An = A + (size_t)n * Hh * 16;
    for (int idx = threadIdx.x; idx < Hh * 16; idx += 256) {
        const int h = idx >> 4, l = idx & 15;
        __nv_bfloat16 hi, lo;
        split_bf16(An[idx], hi, lo);
        const size_t o = ((size_t)(n * 16 + l)) * Hh + h;
        g_AThi[o] = hi;
        g_ATlo[o] = lo;
    }
}

// =====================================================================
// One-time GEMM: P[(n,l)][:] = A^T[(n,l)][:] @ Wattn  (bf16 hi/lo x3)
// =====================================================================
__global__ __launch_bounds__(256, 3) void gemm_P_kernel()
{
    extern __shared__ __align__(128) __nv_bfloat16 dsm[];
    const uint32_t s0 = smem_to_u32(dsm);
    const int tid = threadIdx.x;
    const int lane = tid & 31;
    const int w = tid >> 5;
    const int wm = w & 3, wn = w >> 2;
    const int bn = blockIdx.x * GBN;
    const int bm = blockIdx.y * GBM;

    const int a_row = tid >> 2, a_seg = tid & 3;
    const int b_row = tid >> 2, b_seg = tid & 3;
    const uint32_t aOff = (uint32_t)((wm * 32 + (lane & 15)) * RSTR + (lane >> 4) * 16);
    const int brow = (lane & 7) + ((lane >> 4) << 3);
    const uint32_t bOff = (uint32_t)((wn * 32 + brow) * RSTR + ((lane >> 3) & 1) * 16);

    auto issue = [&](int c, int s) {
        const int kc = c * GBK;
        {
            const size_t o = (size_t)(bn + b_row) * Ktot + 1024 + kc + b_seg * 8;
            CP_ASYNC16(s0 + BH_OFF(s) + b_row * RSTR + b_seg * 16, g_WThi + o);
            CP_ASYNC16(s0 + BL_OFF(s) + b_row * RSTR + b_seg * 16, g_WTlo + o);
        }
#pragma unroll
        for (int r = 0; r < 2; r++) {
            const int m = a_row + r * 64;
            const size_t o = (size_t)(bm + m) * Hh + kc + a_seg * 8;
            const uint32_t d = m * RSTR + a_seg * 16;
            CP_ASYNC16(s0 + AH_OFF(s) + d, g_AThi + o);
            CP_ASYNC16(s0 + AL_OFF(s) + d, g_ATlo + o);
        }
    };

    float acc[2][4][4];
#pragma unroll
    for (int mf = 0; mf < 2; mf++)
#pragma unroll
        for (int nf = 0; nf < 4; nf++)
#pragma unroll
            for (int i = 0; i < 4; i++) acc[mf][nf][i] = 0.0f;

    const int NCH = Hh / GBK;  // 32
    issue(0, 0); CP_COMMIT();
    for (int it = 0; it < NCH; it++) {
        CP_WAIT0();
        __syncthreads();
        if (it + 1 < NCH) { issue(it + 1, (it + 1) & 1); CP_COMMIT(); }
        compute_chunk(s0, it & 1, aOff, bOff, acc);
    }

#pragma unroll
    for (int mf = 0; mf < 2; mf++) {
        const int row0 = bm + wm * 32 + mf * 16 + (lane >> 2);
#pragma unroll
        for (int nf = 0; nf < 4; nf++) {
            const int col = bn + wn * 32 + nf * 8 + (lane & 3) * 2;
            *(float2*)&g_P[(size_t)row0 * G4 + col] =
                make_float2(acc[mf][nf][0], acc[mf][nf][1]);
            *(float2*)&g_P[(size_t)(row0 + 8) * G4 + col] =
                make_float2(acc[mf][nf][2], acc[mf][nf][3]);
        }
    }
}

// =====================================================================
// Init: h0 = mean_l A[n,h,l]; c0 = h0; write g_h fp32 + bf16 hi/lo.
// =====================================================================
__global__ __launch_bounds__(256) void init_kernel(const float* __restrict__ A)
{
    int n = blockIdx.x;
    int tid = threadIdx.x;
    const float* An = A + (size_t)n * Hh * 16;

#pragma unroll
    for (int r = 0; r < 4; r++) {
        int hh = tid + r * 256;
        const float4* ar = (const float4*)(An + (size_t)hh * 16);
        float4 a0 = ar[0], a1 = ar[1], a2 = ar[2], a3 = ar[3];
        float s = a0.x + a0.y + a0.z + a0.w + a1.x + a1.y + a1.z + a1.w
                + a2.x + a2.y + a2.z + a2.w + a3.x + a3.y + a3.z + a3.w;
        s *= (1.0f / 16.0f);
        g_c[(size_t)n * Hh + hh] = s;
        g_h[(size_t)n * Hh + hh] = s;
        __nv_bfloat16 hi, lo;
        split_bf16(s, hi, lo);
        g_Ahi[(size_t)n * Hh + hh] = hi;
        g_Alo[(size_t)n * Hh + hh] = lo;
    }
}

// =====================================================================
// Persistent step loop: 444 CTAs (148 SMs x 3), all resident.
//   bx < 384 : GEMM worker, fixed tile: bn = (bx%64)*64, bm = ((bx/64)%2)*128,
//              kz = bx/128 in {0,1,2}; K range [kz*512, kz*512+512) of KSTEP.
//              kz 0,1 read h; kz 2 reads x_t — branch-uniform per CTA.
//   bx >= 384: attention worker (4-5 batch rows): softmax(A.h/32) then
//              g_pa[n] = sum_l w_l P[(n,l)] — overlapped with GEMM.
//   grid_sync; cooperative LSTM pointwise (3 partials + pa + b); grid_sync.
// =====================================================================
__global__ __launch_bounds__(256, 3) void step_loop_kernel(const float* __restrict__ A,
                                                           const float* __restrict__ b,
                                                           float* __restrict__ out)
{
    extern __shared__ __align__(128) __nv_bfloat16 dsm[];
    __shared__ float red[16][8];
    __shared__ float wsm[16];

    const uint32_t s0 = smem_to_u32(dsm);
    const int tid = threadIdx.x;
    const int lane = tid & 31;
    const int bx = blockIdx.x;

    // GEMM-role constants (fixed per CTA)
    const int w = tid >> 5;
    const int wm = w & 3, wn = w >> 2;
    const int bn = (bx & 63) * GBN;
    const int bm = ((bx >> 6) & 1) * GBM;
    const int kz = bx >> 7;                    // 0,1,2 for bx<384
    const int kbase = kz * 512;
    const int a_row = tid >> 2, a_seg = tid & 3;
    const int b_row = tid >> 2, b_seg = tid & 3;
    const uint32_t aOff = (uint32_t)((wm * 32 + (lane & 15)) * RSTR + (lane >> 4) * 16);
    const int brow_l = (lane & 7) + ((lane >> 4) << 3);
    const uint32_t bOff = (uint32_t)((wn * 32 + brow_l) * RSTR + ((lane >> 3) & 1) * 16);

    for (int t = 0; t < Tt; t++) {
        if (bx < NGEMM) {
            // ---------------- GEMM role ----------------
            auto issue = [&](int c, int s) {
                const int kg = kbase + c * GBK;                    // 0..1535
                const int kidx = (kg < 1024) ? kg : kg + 1024;     // WT column
                {
                    const size_t o = (size_t)(bn + b_row) * Ktot + kidx + b_seg * 8;
                    CP_ASYNC16(s0 + BH_OFF(s) + b_row * RSTR + b_seg * 16, g_WThi + o);
                    CP_ASYNC16(s0 + BL_OFF(s) + b_row * RSTR + b_seg * 16, g_WTlo + o);
                }
#pragma unroll
                for (int r = 0; r < 2; r++) {
                    const int m = a_row + r * 64;
                    const __nv_bfloat16 *sh, *sl;
                    if (kg < 1024) {
                        const size_t o = (size_t)(bm + m) * Hh + kg + a_seg * 8;
                        sh = g_Ahi + o; sl = g_Alo + o;
                    } else {
                        const size_t o = (size_t)(bm + m) * (Tt * Dd) + (size_t)t * Dd
                                       + (kg - 1024) + a_seg * 8;
                        sh = g_xhi + o; sl = g_xlo + o;
                    }
                    const uint32_t d = m * RSTR + a_seg * 16;
                    CP_ASYNC16(s0 + AH_OFF(s) + d, sh);
                    CP_ASYNC16(s0 + AL_OFF(s) + d, sl);
                }
            };

            float acc[2][4][4];
#pragma unroll
            for (int mf = 0; mf < 2; mf++)
#pragma unroll
                for (int nf = 0; nf < 4; nf++)
#pragma unroll
                    for (int i = 0; i < 4; i++) acc[mf][nf][i] = 0.0f;

            const int NCH = 512 / GBK;  // 16
            issue(0, 0); CP_COMMIT();
            for (int it = 0; it < NCH; it++) {
                CP_WAIT0();
                __syncthreads();
                if (it + 1 < NCH) { issue(it + 1, (it + 1) & 1); CP_COMMIT(); }
                compute_chunk(s0, it & 1, aOff, bOff, acc);
            }

            float* gpart = g_gp + (size_t)kz * Nn * G4;
#pragma unroll
            for (int mf = 0; mf < 2; mf++) {
                const int row0 = bm + wm * 32 + mf * 16 + (lane >> 2);
#pragma unroll
                for (int nf = 0; nf < 4; nf++) {
                    const int col = bn + wn * 32 + nf * 8 + (lane & 3) * 2;
                    *(float2*)&gpart[(size_t)row0 * G4 + col] =
                        make_float2(acc[mf][nf][0], acc[mf][nf][1]);
                    *(float2*)&gpart[(size_t)(row0 + 8) * G4 + col] =
                        make_float2(acc[mf][nf][2], acc[mf][nf][3]);
                }
            }
        } else {
            // ---------------- attention / P-sum role ----------------
            const int a_id = bx - NGEMM;          // 0..59
            const int n0 = (a_id * Nn) / NATT;
            const int n1 = ((a_id + 1) * Nn) / NATT;
#pragma unroll 1
            for (int n = n0; n < n1; n++) {
                const float* An = A + (size_t)n * Hh * 16;
                const float* hn = g_h + (size_t)n * Hh;

                float sc[16];
#pragma unroll
                for (int l = 0; l < 16; l++) sc[l] = 0.0f;
#pragma unroll
                for (int r = 0; r < 4; r++) {
                    int hh = tid + r * 256;
                    float hv = hn[hh];
                    const float4* ar = (const float4*)(An + (size_t)hh * 16);
                    float4 a0 = ar[0], a1 = ar[1], a2 = ar[2], a3 = ar[3];
                    sc[0]  += a0.x * hv; sc[1]  += a0.y * hv; sc[2]  += a0.z * hv; sc[3]  += a0.w * hv;
                    sc[4]  += a1.x * hv; sc[5]  += a1.y * hv; sc[6]  += a1.z * hv; sc[7]  += a1.w * hv;
                    sc[8]  += a2.x * hv; sc[9]  += a2.y * hv; sc[10] += a2.z * hv; sc[11] += a2.w * hv;
                    sc[12] += a3.x * hv; sc[13] += a3.y * hv; sc[14] += a3.z * hv; sc[15] += a3.w * hv;
                }
#pragma unroll
                for (int l = 0; l < 16; l++) {
#pragma unroll
                    for (int off = 16; off > 0; off >>= 1)
                        sc[l] += __shfl_xor_sync(0xffffffffu, sc[l], off);
                }
                int warp = tid >> 5;
                if (lane == 0) {
#pragma unroll
                    for (int l = 0; l < 16; l++) red[l][warp] = sc[l];
                }
                __syncthreads();
                if (tid == 0) {
                    float s[16];
                    float mx = -1e30f;
#pragma unroll
                    for (int l = 0; l < 16; l++) {
                        float v = 0.0f;
#pragma unroll
                        for (int w2 = 0; w2 < 8; w2++) v += red[l][w2];
                        v *= 0.03125f;  // 1/sqrt(1024)
                        s[l] = v;
                        mx = fmaxf(mx, v);
                    }
                    float sum = 0.0f;
#pragma unroll
                    for (int l = 0; l < 16; l++) { float e = __expf(s[l] - mx); s[l] = e; sum += e; }
                    float inv = 1.0f / sum;
#pragma unroll
                    for (int l = 0; l < 16; l++) wsm[l] = s[l] * inv;
                }
                __syncthreads();

                float s[16];
#pragma unroll
                for (int i = 0; i < 16; i++) s[i] = 0.0f;
#pragma unroll
                for (int l = 0; l < 16; l++) {
                    const float wl = wsm[l];
                    const float* Pr = g_P + ((size_t)(n * 16 + l)) * G4;
#pragma unroll
                    for (int i = 0; i < 16; i++) s[i] += wl * Pr[tid + i * 256];
                }
                float* pa = g_pa + (size_t)n * G4;
#pragma unroll
                for (int i = 0; i < 16; i++) pa[tid + i * 256] = s[i];
                __syncthreads();
            }
        }

        grid_sync();   // gp (3 slots) + pa complete and visible

        // ---------------- cooperative LSTM pointwise ----------------
        for (int e = bx * 256 + tid; e < Nn * Hh; e += NBLK * 256) {
            const int n = e >> 10;
            const int hh = e & 1023;
            const size_t base = (size_t)n * G4;
            const float* g0 = g_gp + base;
            const float* g1 = g_gp + (size_t)Nn * G4 + base;
            const float* g2 = g_gp + (size_t)2 * Nn * G4 + base;
            const float* pa = g_pa + base;
            float gv[4];
#pragma unroll
            for (int gg = 0; gg < 4; gg++) {
                const int o = gg * Hh + hh;
                gv[gg] = ((g0[o] + g1[o]) + (g2[o] + pa[o])) + b[o];
            }
            float c = g_c[e];
            float cn = sigmoidf_(gv[1]) * c + sigmoidf_(gv[0]) * tanhf_(gv[3]);
            float hn = sigmoidf_(gv[2]) * tanhf_(cn);
            g_c[e] = cn;
            g_h[e] = hn;
            out[(size_t)n * Tt * Hh + (size_t)t * Hh + hh] = hn;
            __nv_bfloat16 hi, lo;
            split_bf16(hn, hi, lo);
            g_Ahi[e] = hi;
            g_Alo[e] = lo;
        }

        grid_sync();   // h_{t+1} visible to everyone
    }
}

// =====================================================================
// launch
// =====================================================================
extern "C" void kernel_launch(void* const* d_in, const int* in_sizes, int n_in,
                              void* d_out, int out_size)
{
    (void)in_sizes; (void)n_in; (void)out_size;
    const float* x     = (const float*)d_in[0];  // (N, T, D)
    const float* A     = (const float*)d_in[1];  // (N, H, 4, 4)
    const float* Wx    = (const float*)d_in[2];  // (D, 4H)
    const float* Wh    = (const float*)d_in[3];  // (H, 4H)
    const float* Wattn = (const float*)d_in[4];  // (H, 4H)
    const float* b     = (const float*)d_in[5];  // (4H,)
    float* out = (float*)d_out;                  // (N, T, H)

    cudaFuncSetAttribute(gemm_P_kernel,
                         cudaFuncAttributeMaxDynamicSharedMemorySize, SMEM_DYN);
    cudaFuncSetAttribute(step_loop_kernel,
                         cudaFuncAttributeMaxDynamicSharedMemorySize, SMEM_DYN);

    // one-time prep
    dim3 wgrid(G4 / 32, Ktot / 32);
    wconv_kernel<<<wgrid, 256>>>(Wx, Wh, Wattn);
    xconv_kernel<<<8192, 256>>>(x);
    aconv_kernel<<<Nn, 256>>>(A);
    gemm_P_kernel<<<dim3(G4 / GBN, (Nn * 16) / GBM), 256, SMEM_DYN>>>();
    init_kernel<<<Nn, 256>>>(A);

    // the whole 128-step recurrence in ONE persistent launch
    step_loop_kernel<<<NBLK, 256, SMEM_DYN>>>(A, b, out);
}

// round 14
// speedup vs baseline: 1.8474x; 1.3819x over previous
#include <cuda_runtime.h>
#include <cuda_bf16.h>
#include <cstdint>
#include <cstddef>

// Problem dims
#define Nn 256
#define Tt 128
#define Dd 512
#define Hh 1024
#define G4 4096            // 4*H
#define Ktot 2560          // W^T cols: Wh (0..1023) | Wattn (1024..2047) | Wx (2048..2559)
#define KSTEP 1536         // per-step GEMM K: h (0..1023) | x_t (1024..1535)

#define NBLK 384           // persistent grid: 256 GEMM + 128 attn CTAs (<= 148*3 resident)

// ---------------- scratch (device globals: allocation-free rule) ----------------
__device__ float g_c[Nn * Hh];                          // LSTM cell state (fp32)
__device__ float g_h[Nn * Hh];                          // current h (fp32)
__device__ float g_gp[(size_t)2 * Nn * G4];             // per-step GEMM partials (2 K-splits)
__device__ float g_pa[(size_t)Nn * G4];                 // attn contribution to gates
__device__ float g_P[(size_t)Nn * 16 * G4];             // P[(n,l)][col] = A[n,:,l] @ Wattn
__device__ __align__(16) __nv_bfloat16 g_Ahi[(size_t)Nn * Hh];        // h hi
__device__ __align__(16) __nv_bfloat16 g_Alo[(size_t)Nn * Hh];        // h lo
__device__ __align__(16) __nv_bfloat16 g_AThi[(size_t)Nn * 16 * Hh];  // A^T [(n,l)][h] hi
__device__ __align__(16) __nv_bfloat16 g_ATlo[(size_t)Nn * 16 * Hh];  // A^T [(n,l)][h] lo
__device__ __align__(16) __nv_bfloat16 g_xhi[(size_t)Nn * Tt * Dd];   // x hi
__device__ __align__(16) __nv_bfloat16 g_xlo[(size_t)Nn * Tt * Dd];   // x lo
__device__ __align__(16) __nv_bfloat16 g_WThi[(size_t)G4 * Ktot];     // W^T hi: [n][k], K-major
__device__ __align__(16) __nv_bfloat16 g_WTlo[(size_t)G4 * Ktot];     // W^T lo

// grid barrier state
__device__ unsigned g_bar_count = 0;
__device__ unsigned g_bar_gen = 0;

// ---------------- PTX helpers (sm_80+ baseline features only) ----------------
__device__ __forceinline__ uint32_t smem_to_u32(const void* p) {
    uint32_t a;
    asm("{ .reg .u64 t; cvta.to.shared.u64 t, %1; cvt.u32.u64 %0, t; }" : "=r"(a) : "l"(p));
    return a;
}
#define CP_ASYNC16(dst, src) \
    asm volatile("cp.async.cg.shared.global [%0], [%1], 16;" :: "r"(dst), "l"(src))
#define CP_COMMIT() asm volatile("cp.async.commit_group;" ::: "memory")
#define CP_WAIT0()  asm volatile("cp.async.wait_group 0;" ::: "memory")
#define LDSM_X4(r0, r1, r2, r3, addr)                                             \
    asm volatile("ldmatrix.sync.aligned.m8n8.x4.shared.b16 {%0,%1,%2,%3}, [%4];"  \
        : "=r"(r0), "=r"(r1), "=r"(r2), "=r"(r3) : "r"(addr))

__device__ __forceinline__ void mma16816(float* c, const uint32_t* a,
                                         uint32_t b0, uint32_t b1) {
    asm volatile(
        "mma.sync.aligned.m16n8k16.row.col.f32.bf16.bf16.f32 "
        "{%0,%1,%2,%3}, {%4,%5,%6,%7}, {%8,%9}, {%0,%1,%2,%3};"
        : "+f"(c[0]), "+f"(c[1]), "+f"(c[2]), "+f"(c[3])
        : "r"(a[0]), "r"(a[1]), "r"(a[2]), "r"(a[3]), "r"(b0), "r"(b1));
}

// Software grid barrier. Safe: all NBLK CTAs co-resident (384 <= 148 SMs x 3).
__device__ __forceinline__ void grid_sync() {
    __syncthreads();
    if (threadIdx.x == 0) {
        __threadfence();
        unsigned g = *(volatile unsigned*)&g_bar_gen;
        unsigned prev = atomicAdd(&g_bar_count, 1u);
        if (prev == NBLK - 1) {
            g_bar_count = 0;
            __threadfence();
            *(volatile unsigned*)&g_bar_gen = g + 1;
        } else {
            while (*(volatile unsigned*)&g_bar_gen == g) { __nanosleep(64); }
        }
    }
    __syncthreads();
}

// ---------------- math helpers ----------------
__device__ __forceinline__ float sigmoidf_(float x) { return 1.0f / (1.0f + __expf(-x)); }
__device__ __forceinline__ float tanhf_(float x) {
    float e = __expf(2.0f * x);
    return 1.0f - 2.0f / (e + 1.0f);
}
__device__ __forceinline__ void split_bf16(float v, __nv_bfloat16& hi, __nv_bfloat16& lo) {
    hi = __float2bfloat16(v);
    lo = __float2bfloat16(v - __bfloat162float(hi));
}

// ---------------- shared GEMM tiling ----------------
#define GBM 128
#define GBN 64
#define GBK 32
#define RSTR 80              // smem row stride bytes (32 bf16 + 8 pad)
#define STG 30720            // bytes per pipeline stage
#define AH_OFF(s) ((s) * STG)
#define AL_OFF(s) ((s) * STG + 10240)
#define BH_OFF(s) ((s) * STG + 20480)
#define BL_OFF(s) ((s) * STG + 25600)
#define SMEM_DYN (2 * STG)   // 61440 -> 3 CTAs/SM

// Fragment compute for one chunk stage.
__device__ __forceinline__ void compute_chunk(uint32_t s0, int stage,
                                              uint32_t aOff, uint32_t bOff,
                                              float acc[2][4][4])
{
    const uint32_t ah = s0 + AH_OFF(stage) + aOff;
    const uint32_t al = s0 + AL_OFF(stage) + aOff;
    const uint32_t bh = s0 + BH_OFF(stage) + bOff;
    const uint32_t bl = s0 + BL_OFF(stage) + bOff;
#pragma unroll
    for (int ks = 0; ks < 2; ks++) {
        const uint32_t ko = ks * 32;   // 16 elems * 2B
        uint32_t ahf[2][4], alf[2][4];
        uint32_t bhf[2][4], blf[2][4];
        LDSM_X4(ahf[0][0], ahf[0][1], ahf[0][2], ahf[0][3], ah + ko);
        LDSM_X4(ahf[1][0], ahf[1][1], ahf[1][2], ahf[1][3], ah + 16 * RSTR + ko);
        LDSM_X4(bhf[0][0], bhf[0][1], bhf[0][2], bhf[0][3], bh + ko);
        LDSM_X4(bhf[1][0], bhf[1][1], bhf[1][2], bhf[1][3], bh + 16 * RSTR + ko);
        LDSM_X4(blf[0][0], blf[0][1], blf[0][2], blf[0][3], bl + ko);
        LDSM_X4(blf[1][0], blf[1][1], blf[1][2], blf[1][3], bl + 16 * RSTR + ko);
        LDSM_X4(alf[0][0], alf[0][1], alf[0][2], alf[0][3], al + ko);
        LDSM_X4(alf[1][0], alf[1][1], alf[1][2], alf[1][3], al + 16 * RSTR + ko);
#pragma unroll
        for (int mf = 0; mf < 2; mf++) {
#pragma unroll
            for (int nf = 0; nf < 4; nf++) {
                const uint32_t b0 = bhf[nf >> 1][(nf & 1) * 2];
                const uint32_t b1 = bhf[nf >> 1][(nf & 1) * 2 + 1];
                mma16816(acc[mf][nf], ahf[mf], b0, b1);           // hi*hi
                mma16816(acc[mf][nf], alf[mf], b0, b1);           // lo*hi
                mma16816(acc[mf][nf], ahf[mf],                    // hi*lo
                         blf[nf >> 1][(nf & 1) * 2], blf[nf >> 1][(nf & 1) * 2 + 1]);
            }
        }
    }
}

// =====================================================================
// One-time: W^T hi/lo. WT[n][k] = bf16split(W[k][n]); K rows: Wh|Wattn|Wx
// =====================================================================
__global__ __launch_bounds__(256) void wconv_kernel(const float* __restrict__ Wx,
                                                    const float* __restrict__ Wh,
                                                    const float* __restrict__ Wattn)
{
    __shared__ float tile[32][33];
    const int nt = blockIdx.x * 32;
    const int kt = blockIdx.y * 32;
    const int tx = threadIdx.x & 31, ty = threadIdx.x >> 5;
#pragma unroll
    for (int r = 0; r < 4; r++) {
        int k = kt + ty + r * 8;
        int n = nt + tx;
        const float* src;
        if (k < 1024)       src = Wh    + (size_t)k * G4;
        else if (k < 2048)  src = Wattn + (size_t)(k - 1024) * G4;
        else                src = Wx    + (size_t)(k - 2048) * G4;
        tile[ty + r * 8][tx] = src[n];
    }
    __syncthreads();
#pragma unroll
    for (int r = 0; r < 4; r++) {
        int n = nt + ty + r * 8;
        int k = kt + tx;
        float v = tile[tx][ty + r * 8];
        __nv_bfloat16 hi, lo;
        split_bf16(v, hi, lo);
        g_WThi[(size_t)n * Ktot + k] = hi;
        g_WTlo[(size_t)n * Ktot + k] = lo;
    }
}

// One-time: x -> bf16 hi/lo (float4 vectorized)
__global__ __launch_bounds__(256) void xconv_kernel(const float* __restrict__ x)
{
    const size_t total4 = (size_t)Nn * Tt * Dd / 4;
    for (size_t i = (size_t)blockIdx.x * blockDim.x + threadIdx.x; i < total4;
         i += (size_t)gridDim.x * blockDim.x) {
        float4 v = ((const float4*)x)[i];
        __nv_bfloat16 h4[4], l4[4];
        split_bf16(v.x, h4[0], l4[0]);
        split_bf16(v.y, h4[1], l4[1]);
        split_bf16(v.z, h4[2], l4[2]);
        split_bf16(v.w, h4[3], l4[3]);
        ((uint2*)g_xhi)[i] = *(uint2*)h4;
        ((uint2*)g_xlo)[i] = *(uint2*)l4;
    }
}

// One-time: A[n][h][l] -> A^T [(n*16+l)][h] bf16 hi/lo
__global__ __launch_bounds__(256) void aconv_kernel(const float* __restrict__ A)
{
    const int n = blockIdx.x;
    const float* An = A + (size_t)n * Hh * 16;
    for (int idx = threadIdx.x; idx < Hh * 16; idx += 256) {
        const int h = idx >> 4, l = idx & 15;
        __nv_bfloat16 hi, lo;
        split_bf16(An[idx], hi, lo);
        const size_t o = ((size_t)(n * 16 + l)) * Hh + h;
        g_AThi[o] = hi;
        g_ATlo[o] = lo;
    }
}

// =====================================================================
// One-time GEMM: P[(n,l)][:] = A^T[(n,l)][:] @ Wattn  (bf16 hi/lo x3)
// =====================================================================
__global__ __launch_bounds__(256, 3) void gemm_P_kernel()
{
    extern __shared__ __align__(128) __nv_bfloat16 dsm[];
    const uint32_t s0 = smem_to_u32(dsm);
    const int tid = threadIdx.x;
    const int lane = tid & 31;
    const int w = tid >> 5;
    const int wm = w & 3, wn = w >> 2;
    const int bn = blockIdx.x * GBN;
    const int bm = blockIdx.y * GBM;

    const int a_row = tid >> 2, a_seg = tid & 3;
    const int b_row = tid >> 2, b_seg = tid & 3;
    const uint32_t aOff = (uint32_t)((wm * 32 + (lane & 15)) * RSTR + (lane >> 4) * 16);
    const int brow = (lane & 7) + ((lane >> 4) << 3);
    const uint32_t bOff = (uint32_t)((wn * 32 + brow) * RSTR + ((lane >> 3) & 1) * 16);

    auto issue = [&](int c, int s) {
        const int kc = c * GBK;
        {
            const size_t o = (size_t)(bn + b_row) * Ktot + 1024 + kc + b_seg * 8;
            CP_ASYNC16(s0 + BH_OFF(s) + b_row * RSTR + b_seg * 16, g_WThi + o);
            CP_ASYNC16(s0 + BL_OFF(s) + b_row * RSTR + b_seg * 16, g_WTlo + o);
        }
#pragma unroll
        for (int r = 0; r < 2; r++) {
            const int m = a_row + r * 64;
            const size_t o = (size_t)(bm + m) * Hh + kc + a_seg * 8;
            const uint32_t d = m * RSTR + a_seg * 16;
            CP_ASYNC16(s0 + AH_OFF(s) + d, g_AThi + o);
            CP_ASYNC16(s0 + AL_OFF(s) + d, g_ATlo + o);
        }
    };

    float acc[2][4][4];
#pragma unroll
    for (int mf = 0; mf < 2; mf++)
#pragma unroll
        for (int nf = 0; nf < 4; nf++)
#pragma unroll
            for (int i = 0; i < 4; i++) acc[mf][nf][i] = 0.0f;

    const int NCH = Hh / GBK;  // 32
    issue(0, 0); CP_COMMIT();
    for (int it = 0; it < NCH; it++) {
        CP_WAIT0();
        __syncthreads();
        if (it + 1 < NCH) { issue(it + 1, (it + 1) & 1); CP_COMMIT(); }
        compute_chunk(s0, it & 1, aOff, bOff, acc);
    }

#pragma unroll
    for (int mf = 0; mf < 2; mf++) {
        const int row0 = bm + wm * 32 + mf * 16 + (lane >> 2);
#pragma unroll
        for (int nf = 0; nf < 4; nf++) {
            const int col = bn + wn * 32 + nf * 8 + (lane & 3) * 2;
            *(float2*)&g_P[(size_t)row0 * G4 + col] =
                make_float2(acc[mf][nf][0], acc[mf][nf][1]);
            *(float2*)&g_P[(size_t)(row0 + 8) * G4 + col] =
                make_float2(acc[mf][nf][2], acc[mf][nf][3]);
        }
    }
}

// =====================================================================
// Init: h0 = mean_l A[n,h,l]; c0 = h0; write g_h fp32 + bf16 hi/lo.
// =====================================================================
__global__ __launch_bounds__(256) void init_kernel(const float* __restrict__ A)
{
    int n = blockIdx.x;
    int tid = threadIdx.x;
    const float* An = A + (size_t)n * Hh * 16;

#pragma unroll
    for (int r = 0; r < 4; r++) {
        int hh = tid + r * 256;
        const float4* ar = (const float4*)(An + (size_t)hh * 16);
        float4 a0 = ar[0], a1 = ar[1], a2 = ar[2], a3 = ar[3];
        float s = a0.x + a0.y + a0.z + a0.w + a1.x + a1.y + a1.z + a1.w
                + a2.x + a2.y + a2.z + a2.w + a3.x + a3.y + a3.z + a3.w;
        s *= (1.0f / 16.0f);
        g_c[(size_t)n * Hh + hh] = s;
        g_h[(size_t)n * Hh + hh] = s;
        __nv_bfloat16 hi, lo;
        split_bf16(s, hi, lo);
        g_Ahi[(size_t)n * Hh + hh] = hi;
        g_Alo[(size_t)n * Hh + hh] = lo;
    }
}

// =====================================================================
// Persistent step loop: 384 CTAs, all resident (identical structure to the
// 6108us R11 kernel; LSTM phase vectorized to float4).
//   bx <  256: GEMM  gp[kz] = [h|x_t](:, Kz) @ [Wh;Wx](Kz, :), K=1536 split x2
//   bx >= 256: attention (2 n each): softmax(A.h/32); g_pa = sum_l w_l P[(n,l)]
//   then grid_sync; cooperative LSTM pointwise; grid_sync; next t.
// =====================================================================
__global__ __launch_bounds__(256, 3) void step_loop_kernel(const float* __restrict__ A,
                                                           const float* __restrict__ b,
                                                           float* __restrict__ out)
{
    extern __shared__ __align__(128) __nv_bfloat16 dsm[];
    __shared__ float red[16][8];
    __shared__ float wsm[16];

    const uint32_t s0 = smem_to_u32(dsm);
    const int tid = threadIdx.x;
    const int lane = tid & 31;
    const int bx = blockIdx.x;

    // GEMM-role constants
    const int w = tid >> 5;
    const int wm = w & 3, wn = w >> 2;
    const int bn = (bx & 63) * GBN;
    const int bm = ((bx >> 6) & 1) * GBM;
    const int kz = (bx >> 7) & 1;
    const int kbase = kz * (KSTEP / 2);      // 0 or 768
    const int a_row = tid >> 2, a_seg = tid & 3;
    const int b_row = tid >> 2, b_seg = tid & 3;
    const uint32_t aOff = (uint32_t)((wm * 32 + (lane & 15)) * RSTR + (lane >> 4) * 16);
    const int brow_l = (lane & 7) + ((lane >> 4) << 3);
    const uint32_t bOff = (uint32_t)((wn * 32 + brow_l) * RSTR + ((lane >> 3) & 1) * 16);

    for (int t = 0; t < Tt; t++) {
        if (bx < 256) {
            // ---------------- GEMM role ----------------
            auto issue = [&](int c, int s) {
                const int kg = kbase + c * GBK;                    // 0..1535
                const int kidx = (kg < 1024) ? kg : kg + 1024;     // WT column
                {
                    const size_t o = (size_t)(bn + b_row) * Ktot + kidx + b_seg * 8;
                    CP_ASYNC16(s0 + BH_OFF(s) + b_row * RSTR + b_seg * 16, g_WThi + o);
                    CP_ASYNC16(s0 + BL_OFF(s) + b_row * RSTR + b_seg * 16, g_WTlo + o);
                }
#pragma unroll
                for (int r = 0; r < 2; r++) {
                    const int m = a_row + r * 64;
                    const __nv_bfloat16 *sh, *sl;
                    if (kg < 1024) {
                        const size_t o = (size_t)(bm + m) * Hh + kg + a_seg * 8;
                        sh = g_Ahi + o; sl = g_Alo + o;
                    } else {
                        const size_t o = (size_t)(bm + m) * (Tt * Dd) + (size_t)t * Dd
                                       + (kg - 1024) + a_seg * 8;
                        sh = g_xhi + o; sl = g_xlo + o;
                    }
                    const uint32_t d = m * RSTR + a_seg * 16;
                    CP_ASYNC16(s0 + AH_OFF(s) + d, sh);
                    CP_ASYNC16(s0 + AL_OFF(s) + d, sl);
                }
            };

            float acc[2][4][4];
#pragma unroll
            for (int mf = 0; mf < 2; mf++)
#pragma unroll
                for (int nf = 0; nf < 4; nf++)
#pragma unroll
                    for (int i = 0; i < 4; i++) acc[mf][nf][i] = 0.0f;

            const int NCH = (KSTEP / 2) / GBK;  // 24
            issue(0, 0); CP_COMMIT();
            for (int it = 0; it < NCH; it++) {
                CP_WAIT0();
                __syncthreads();
                if (it + 1 < NCH) { issue(it + 1, (it + 1) & 1); CP_COMMIT(); }
                compute_chunk(s0, it & 1, aOff, bOff, acc);
            }

            float* gpart = g_gp + (size_t)kz * Nn * G4;
#pragma unroll
            for (int mf = 0; mf < 2; mf++) {
                const int row0 = bm + wm * 32 + mf * 16 + (lane >> 2);
#pragma unroll
                for (int nf = 0; nf < 4; nf++) {
                    const int col = bn + wn * 32 + nf * 8 + (lane & 3) * 2;
                    *(float2*)&gpart[(size_t)row0 * G4 + col] =
                        make_float2(acc[mf][nf][0], acc[mf][nf][1]);
                    *(float2*)&gpart[(size_t)(row0 + 8) * G4 + col] =
                        make_float2(acc[mf][nf][2], acc[mf][nf][3]);
                }
            }
        } else {
            // ---------------- attention / P-sum role ----------------
            const int flat = bx - 256;   // 0..127
#pragma unroll 1
            for (int sub = 0; sub < 2; sub++) {
                const int n = flat * 2 + sub;
                const float* An = A + (size_t)n * Hh * 16;
                const float* hn = g_h + (size_t)n * Hh;

                float sc[16];
#pragma unroll
                for (int l = 0; l < 16; l++) sc[l] = 0.0f;
#pragma unroll
                for (int r = 0; r < 4; r++) {
                    int hh = tid + r * 256;
                    float hv = hn[hh];
                    const float4* ar = (const float4*)(An + (size_t)hh * 16);
                    float4 a0 = ar[0], a1 = ar[1], a2 = ar[2], a3 = ar[3];
                    sc[0]  += a0.x * hv; sc[1]  += a0.y * hv; sc[2]  += a0.z * hv; sc[3]  += a0.w * hv;
                    sc[4]  += a1.x * hv; sc[5]  += a1.y * hv; sc[6]  += a1.z * hv; sc[7]  += a1.w * hv;
                    sc[8]  += a2.x * hv; sc[9]  += a2.y * hv; sc[10] += a2.z * hv; sc[11] += a2.w * hv;
                    sc[12] += a3.x * hv; sc[13] += a3.y * hv; sc[14] += a3.z * hv; sc[15] += a3.w * hv;
                }
#pragma unroll
                for (int l = 0; l < 16; l++) {
#pragma unroll
                    for (int off = 16; off > 0; off >>= 1)
                        sc[l] += __shfl_xor_sync(0xffffffffu, sc[l], off);
                }
                int warp = tid >> 5;
                if (lane == 0) {
#pragma unroll
                    for (int l = 0; l < 16; l++) red[l][warp] = sc[l];
                }
                __syncthreads();
                if (tid == 0) {
                    float s[16];
                    float mx = -1e30f;
#pragma unroll
                    for (int l = 0; l < 16; l++) {
                        float v = 0.0f;
#pragma unroll
                        for (int w2 = 0; w2 < 8; w2++) v += red[l][w2];
                        v *= 0.03125f;  // 1/sqrt(1024)
                        s[l] = v;
                        mx = fmaxf(mx, v);
                    }
                    float sum = 0.0f;
#pragma unroll
                    for (int l = 0; l < 16; l++) { float e = __expf(s[l] - mx); s[l] = e; sum += e; }
                    float inv = 1.0f / sum;
#pragma unroll
                    for (int l = 0; l < 16; l++) wsm[l] = s[l] * inv;
                }
                __syncthreads();

                float s[16];
#pragma unroll
                for (int i = 0; i < 16; i++) s[i] = 0.0f;
#pragma unroll
                for (int l = 0; l < 16; l++) {
                    const float wl = wsm[l];
                    const float* Pr = g_P + ((size_t)(n * 16 + l)) * G4;
#pragma unroll
                    for (int i = 0; i < 16; i++) s[i] += wl * Pr[tid + i * 256];
                }
                float* pa = g_pa + (size_t)n * G4;
#pragma unroll
                for (int i = 0; i < 16; i++) pa[tid + i * 256] = s[i];
                __syncthreads();
            }
        }

        grid_sync();   // gp + pa complete and visible

        // ---------------- cooperative LSTM pointwise (float4) ----------------
        {
            const int nvec = (Nn * Hh) / 4;   // 65536
            for (int e4 = bx * 256 + tid; e4 < nvec; e4 += NBLK * 256) {
                const int n = e4 >> 8;
                const int hh = (e4 & 255) * 4;
                const size_t base = (size_t)n * G4;
                const float* g0 = g_gp + base;
                const float* g1 = g_gp + (size_t)Nn * G4 + base;
                const float* pa = g_pa + base;

                float4 gv[4];
#pragma unroll
                for (int gg = 0; gg < 4; gg++) {
                    const int o = gg * Hh + hh;
                    float4 a0 = *(const float4*)(g0 + o);
                    float4 a1 = *(const float4*)(g1 + o);
                    float4 pp = *(const float4*)(pa + o);
                    float4 bb = *(const float4*)(b + o);
                    gv[gg].x = (a0.x + a1.x) + (pp.x + bb.x);
                    gv[gg].y = (a0.y + a1.y) + (pp.y + bb.y);
                    gv[gg].z = (a0.z + a1.z) + (pp.z + bb.z);
                    gv[gg].w = (a0.w + a1.w) + (pp.w + bb.w);
                }
                const size_t eh = (size_t)n * Hh + hh;
                float4 cv = *(const float4*)(g_c + eh);
                float4 hv;
                {
                    float cn = sigmoidf_(gv[1].x) * cv.x + sigmoidf_(gv[0].x) * tanhf_(gv[3].x);
                    hv.x = sigmoidf_(gv[2].x) * tanhf_(cn); cv.x = cn;
                    cn = sigmoidf_(gv[1].y) * cv.y + sigmoidf_(gv[0].y) * tanhf_(gv[3].y);
                    hv.y = sigmoidf_(gv[2].y) * tanhf_(cn); cv.y = cn;
                    cn = sigmoidf_(gv[1].z) * cv.z + sigmoidf_(gv[0].z) * tanhf_(gv[3].z);
                    hv.z = sigmoidf_(gv[2].z) * tanhf_(cn); cv.z = cn;
                    cn = sigmoidf_(gv[1].w) * cv.w + sigmoidf_(gv[0].w) * tanhf_(gv[3].w);
                    hv.w = sigmoidf_(gv[2].w) * tanhf_(cn); cv.w = cn;
                }
                *(float4*)(g_c + eh) = cv;
                *(float4*)(g_h + eh) = hv;
                *(float4*)(out + (size_t)n * Tt * Hh + (size_t)t * Hh + hh) = hv;
                __nv_bfloat16 h4[4], l4[4];
                split_bf16(hv.x, h4[0], l4[0]);
                split_bf16(hv.y, h4[1], l4[1]);
                split_bf16(hv.z, h4[2], l4[2]);
                split_bf16(hv.w, h4[3], l4[3]);
                *(uint2*)(g_Ahi + eh) = *(uint2*)h4;
                *(uint2*)(g_Alo + eh) = *(uint2*)l4;
            }
        }

        grid_sync();   // h_{t+1} visible to everyone
    }
}

// =====================================================================
// launch
// =====================================================================
extern "C" void kernel_launch(void* const* d_in, const int* in_sizes, int n_in,
                              void* d_out, int out_size)
{
    (void)in_sizes; (void)n_in; (void)out_size;
    const float* x     = (const float*)d_in[0];  // (N, T, D)
    const float* A     = (const float*)d_in[1];  // (N, H, 4, 4)
    const float* Wx    = (const float*)d_in[2];  // (D, 4H)
    const float* Wh    = (const float*)d_in[3];  // (H, 4H)
    const float* Wattn = (const float*)d_in[4];  // (H, 4H)
    const float* b     = (const float*)d_in[5];  // (4H,)
    float* out = (float*)d_out;                  // (N, T, H)

    cudaFuncSetAttribute(gemm_P_kernel,
                         cudaFuncAttributeMaxDynamicSharedMemorySize, SMEM_DYN);
    cudaFuncSetAttribute(step_loop_kernel,
                         cudaFuncAttributeMaxDynamicSharedMemorySize, SMEM_DYN);

    // one-time prep
    dim3 wgrid(G4 / 32, Ktot / 32);
    wconv_kernel<<<wgrid, 256>>>(Wx, Wh, Wattn);
    xconv_kernel<<<8192, 256>>>(x);
    aconv_kernel<<<Nn, 256>>>(A);
    gemm_P_kernel<<<dim3(G4 / GBN, (Nn * 16) / GBM), 256, SMEM_DYN>>>();
    init_kernel<<<Nn, 256>>>(A);

    // the whole 128-step recurrence in ONE persistent launch
    step_loop_kernel<<<NBLK, 256, SMEM_DYN>>>(A, b, out);
}